// round 3
// baseline (speedup 1.0000x reference)
#include <cuda_runtime.h>
#include <cstdint>

// exp(X) for batched 32x32 symmetric fp32 via scaling-and-squaring, degree-8
// Paterson-Stockmeyer Taylor. TWO matrices per warp (half-warp h owns matrix h,
// lane owns columns jj and jj+16). Only TWO smem buffers:
//   A: mm A-operand chain  X -> Z -> P
//   E: Xs (stage-1 A-operand + per-lane coeff source), later recycled to B0.
// All Horner B-operands stay in registers; commutativity (polys in X) lets
// every PS matmul use the smem-resident factor as the A-operand.

#define STRIDE 36               // floats per smem row (conflict-free, 16B aligned)
#define MOFF   1168             // matrix-1 offset inside a buffer (+16-bank shift)
#define BUFF   2320             // floats per buffer (2 matrices)

typedef unsigned long long u64;

__device__ __forceinline__ u64 pk2(float lo, float hi) {
    u64 r; asm("mov.b64 %0, {%1, %2};" : "=l"(r) : "f"(lo), "f"(hi)); return r;
}
__device__ __forceinline__ void upk2(float& lo, float& hi, u64 v) {
    asm("mov.b64 {%0, %1}, %2;" : "=f"(lo), "=f"(hi) : "l"(v));
}
__device__ __forceinline__ void fma2(u64& d, u64 a, u64 b) {
    asm("fma.rn.f32x2 %0, %1, %2, %0;" : "+l"(d) : "l"(a), "l"(b));
}
__device__ __forceinline__ u64 mul2(u64 a, u64 b) {
    u64 d; asm("mul.rn.f32x2 %0, %1, %2;" : "=l"(d) : "l"(a), "l"(b)); return d;
}

// C(:,c0|c1) = A * b; A rows from smem (broadcast LDS.128, two half-warps hit
// bank-disjoint rows), b columns in registers. First k peeled as mul2.
__device__ __forceinline__ void mm2(uint32_t aBase, const float* bc0, const float* bc1,
                                    u64 acc0[16], u64 acc1[16]) {
    {
        u64 bb0 = pk2(bc0[0], bc0[0]);
        u64 bb1 = pk2(bc1[0], bc1[0]);
#pragma unroll
        for (int q = 0; q < 8; ++q) {
            u64 a0, a1;
            asm volatile("ld.shared.v2.u64 {%0, %1}, [%2];"
                         : "=l"(a0), "=l"(a1) : "r"(aBase + (uint32_t)(q * 16)));
            acc0[2 * q]     = mul2(a0, bb0);
            acc0[2 * q + 1] = mul2(a1, bb0);
            acc1[2 * q]     = mul2(a0, bb1);
            acc1[2 * q + 1] = mul2(a1, bb1);
        }
    }
#pragma unroll
    for (int k = 1; k < 32; ++k) {
        u64 bb0 = pk2(bc0[k], bc0[k]);
        u64 bb1 = pk2(bc1[k], bc1[k]);
        uint32_t ra = aBase + (uint32_t)(k * STRIDE * 4);
#pragma unroll
        for (int q = 0; q < 8; ++q) {
            u64 a0, a1;
            asm volatile("ld.shared.v2.u64 {%0, %1}, [%2];"
                         : "=l"(a0), "=l"(a1) : "r"(ra + (uint32_t)(q * 16)));
            fma2(acc0[2 * q],     a0, bb0);
            fma2(acc0[2 * q + 1], a1, bb0);
            fma2(acc1[2 * q],     a0, bb1);
            fma2(acc1[2 * q + 1], a1, bb1);
        }
    }
}

__global__ void __launch_bounds__(32, 12)
ExpEig_52553219834314_kernel(const float* __restrict__ in,
                             float* __restrict__ out, int B) {
    __shared__ __align__(16) float smem[2 * BUFF];

    const int lane = threadIdx.x;
    const int h = lane >> 4, jj = lane & 15;
    int mat = blockIdx.x * 2 + h;
    const bool alive = (mat < B);
    if (!alive) mat = B - 1;
    const int c0 = jj, c1 = jj + 16;

    float* myA = smem + h * MOFF;          // X -> Z -> P
    float* myE = myA + BUFF;               // Xs -> B0
    const uint32_t aA = (uint32_t)__cvta_generic_to_shared(myA);
    const uint32_t aE = aA + (uint32_t)(BUFF * 4);

    // Load X columns to regs + mirror into A.
    const float* src = in + (size_t)mat * 1024;
    float b0[32], b1[32];
#pragma unroll
    for (int i = 0; i < 32; ++i) { b0[i] = src[i * 32 + c0]; b1[i] = src[i * 32 + c1]; }
#pragma unroll
    for (int i = 0; i < 32; ++i) {
        myA[i * STRIDE + c0] = b0[i];
        myA[i * STRIDE + c1] = b1[i];
    }
    __syncwarp();

    u64 acc0[16], acc1[16];

    // ---- stage 0: X2 = X * X
    mm2(aA, b0, b1, acc0, acc1);

    // Spectral bound: ||X||_2 <= sqrt(min(||X2||_1, ||X2||_F)).
    float rs = 0.f, fb = 0.f;
    {
        float sa = 0.f, sb = 0.f;
#pragma unroll
        for (int p = 0; p < 16; ++p) {
            float t0, t1, u0, u1;
            upk2(t0, t1, acc0[p]); upk2(u0, u1, acc1[p]);
            sa += fabsf(t0) + fabsf(t1);
            sb += fabsf(u0) + fabsf(u1);
            fb += t0 * t0 + t1 * t1 + u0 * u0 + u1 * u1;
        }
        rs = fmaxf(sa, sb);
    }
#pragma unroll
    for (int off = 8; off > 0; off >>= 1) {   // reduce within half-warp
        rs = fmaxf(rs, __shfl_xor_sync(0xffffffffu, rs, off));
        fb += __shfl_xor_sync(0xffffffffu, fb, off);
    }
    float bnd = sqrtf(fminf(rs, sqrtf(fb)));
    bnd = fmaxf(bnd, __shfl_xor_sync(0xffffffffu, bnd, 16));  // uniform across warp
    int e = 0; (void)frexpf(bnd, &e);
    const int kk = e < 0 ? 0 : (e > 24 ? 24 : e);
    const int total = 4 + kk;
    const float s1 = exp2f(-(float)kk), s2 = s1 * s1;

    // E := Xs; b := X2s.
#pragma unroll
    for (int i = 0; i < 32; ++i) {
        myE[i * STRIDE + c0] = b0[i] * s1;
        myE[i * STRIDE + c1] = b1[i] * s1;
    }
#pragma unroll
    for (int p = 0; p < 16; ++p) {
        upk2(b0[2 * p], b0[2 * p + 1], acc0[p]);
        upk2(b1[2 * p], b1[2 * p + 1], acc1[p]);
        b0[2 * p] *= s2; b0[2 * p + 1] *= s2;
        b1[2 * p] *= s2; b1[2 * p + 1] *= s2;
    }
    __syncwarp();

    // ---- stage 1: Z = Xs * X2s   (A-op = E = Xs, B-op = X2s regs)
    mm2(aE, b0, b1, acc0, acc1);
    // A := Z;  b := B2 = I/720 + Xs/5040 + X2s/40320.
#pragma unroll
    for (int p = 0; p < 16; ++p) {
        float z00, z01, z10, z11;
        upk2(z00, z01, acc0[p]); upk2(z10, z11, acc1[p]);
        const int i0 = 2 * p, i1 = 2 * p + 1;
        myA[i0 * STRIDE + c0] = z00; myA[i1 * STRIDE + c0] = z01;
        myA[i0 * STRIDE + c1] = z10; myA[i1 * STRIDE + c1] = z11;
        b0[i0] = (i0 == c0 ? (1.f / 720.f) : 0.f)
               + myE[i0 * STRIDE + c0] * (1.f / 5040.f) + b0[i0] * (1.f / 40320.f);
        b0[i1] = (i1 == c0 ? (1.f / 720.f) : 0.f)
               + myE[i1 * STRIDE + c0] * (1.f / 5040.f) + b0[i1] * (1.f / 40320.f);
        b1[i0] = (i0 == c1 ? (1.f / 720.f) : 0.f)
               + myE[i0 * STRIDE + c1] * (1.f / 5040.f) + b1[i0] * (1.f / 40320.f);
        b1[i1] = (i1 == c1 ? (1.f / 720.f) : 0.f)
               + myE[i1 * STRIDE + c1] * (1.f / 5040.f) + b1[i1] * (1.f / 40320.f);
    }
    __syncwarp();

    // ---- stage 2: T = Z * B2 (= B2*Z, commute)
    mm2(aA, b0, b1, acc0, acc1);
    // b := T + B1,  B1 = 336*B2 - (3/10)I - (1/40)Xs
    // E := B0      = 20160*B2 - 27 I  - 3     Xs   (recycle E; lane-private)
#pragma unroll
    for (int p = 0; p < 16; ++p) {
        float t00, t01, t10, t11;
        upk2(t00, t01, acc0[p]); upk2(t10, t11, acc1[p]);
        const int i0 = 2 * p, i1 = 2 * p + 1;
        {
            float b2 = b0[i0], xs = myE[i0 * STRIDE + c0], kr = (i0 == c0) ? 1.f : 0.f;
            b0[i0] = t00 + 336.f * b2 - 0.3f * kr - 0.025f * xs;
            myE[i0 * STRIDE + c0] = 20160.f * b2 - 27.f * kr - 3.f * xs;
        }
        {
            float b2 = b0[i1], xs = myE[i1 * STRIDE + c0], kr = (i1 == c0) ? 1.f : 0.f;
            b0[i1] = t01 + 336.f * b2 - 0.3f * kr - 0.025f * xs;
            myE[i1 * STRIDE + c0] = 20160.f * b2 - 27.f * kr - 3.f * xs;
        }
        {
            float b2 = b1[i0], xs = myE[i0 * STRIDE + c1], kr = (i0 == c1) ? 1.f : 0.f;
            b1[i0] = t10 + 336.f * b2 - 0.3f * kr - 0.025f * xs;
            myE[i0 * STRIDE + c1] = 20160.f * b2 - 27.f * kr - 3.f * xs;
        }
        {
            float b2 = b1[i1], xs = myE[i1 * STRIDE + c1], kr = (i1 == c1) ? 1.f : 0.f;
            b1[i1] = t11 + 336.f * b2 - 0.3f * kr - 0.025f * xs;
            myE[i1 * STRIDE + c1] = 20160.f * b2 - 27.f * kr - 3.f * xs;
        }
    }
    // no syncwarp needed: E writes are lane-private, A untouched.

    // ---- stage 3: M2 = Z * (B1 + B2 Z) ; P = M2 + B0
    mm2(aA, b0, b1, acc0, acc1);
#pragma unroll
    for (int p = 0; p < 16; ++p) {
        float m00, m01, m10, m11;
        upk2(m00, m01, acc0[p]); upk2(m10, m11, acc1[p]);
        const int i0 = 2 * p, i1 = 2 * p + 1;
        b0[i0] = m00 + myE[i0 * STRIDE + c0];
        b0[i1] = m01 + myE[i1 * STRIDE + c0];
        b1[i0] = m10 + myE[i0 * STRIDE + c1];
        b1[i1] = m11 + myE[i1 * STRIDE + c1];
    }
    __syncwarp();   // all Z reads done before P overwrites A
    if (total > 4) {
#pragma unroll
        for (int i = 0; i < 32; ++i) {
            myA[i * STRIDE + c0] = b0[i];
            myA[i * STRIDE + c1] = b1[i];
        }
    }
    __syncwarp();

    // ---- squarings: P = P * P
    for (int s = 4; s < total; ++s) {
        mm2(aA, b0, b1, acc0, acc1);
#pragma unroll
        for (int p = 0; p < 16; ++p) {
            upk2(b0[2 * p], b0[2 * p + 1], acc0[p]);
            upk2(b1[2 * p], b1[2 * p + 1], acc1[p]);
        }
        __syncwarp();
        if (s < total - 1) {
#pragma unroll
            for (int i = 0; i < 32; ++i) {
                myA[i * STRIDE + c0] = b0[i];
                myA[i * STRIDE + c1] = b1[i];
            }
        }
        __syncwarp();
    }

    if (alive) {
        float* dst = out + (size_t)mat * 1024;
#pragma unroll
        for (int i = 0; i < 32; ++i) {
            dst[i * 32 + c0] = b0[i];
            dst[i * 32 + c1] = b1[i];
        }
    }
}

extern "C" void kernel_launch(void* const* d_in, const int* in_sizes, int n_in,
                              void* d_out, int out_size) {
    (void)n_in; (void)out_size;
    const float* x = (const float*)d_in[0];
    float* out = (float*)d_out;
    const int B = in_sizes[0] / 1024;
    const int ctas = (B + 1) / 2;
    ExpEig_52553219834314_kernel<<<ctas, 32>>>(x, out, B);
}